// round 6
// baseline (speedup 1.0000x reference)
#include <cuda_runtime.h>

// Problem constants
#define B_    8
#define CIN   512
#define COUT  1024
#define P_    2048
#define H_    8
#define DH    128            // COUT / H

// GEMM tiling
#define BM 128
#define BN 128
#define BK 8
#define TM 8
#define TN 8
#define PAD 4
#define LDS_ (BM + PAD)      // 132

// Scratch (device globals: allocation-free per harness rules)
__device__ float g_Y[50331648];      // [3][B][COUT][P]  = 192 MB (Q,K,V pre/post BN)
__device__ float g_S[268435456];     // [B*H][P][P]      = 1 GiB  (attention map)
__device__ float g_scale[3 * COUT];
__device__ float g_shift[3 * COUT];

// ---------------------------------------------------------------------------
// Shared 8x8 register microkernel over a BK slice of As/Bs tiles.
// As/Bs layout: [BK][BM+PAD], As indexed by (k, m), Bs by (k, n).
// ---------------------------------------------------------------------------
__device__ __forceinline__ void micro_fma(const float (&As)[BK][LDS_],
                                          const float (&Bs)[BK][LDS_],
                                          float (&acc)[TM][TN],
                                          int ty, int tx) {
#pragma unroll
    for (int kk = 0; kk < BK; ++kk) {
        float4 a0 = *(const float4*)&As[kk][ty * TM];
        float4 a1 = *(const float4*)&As[kk][ty * TM + 4];
        float4 b0 = *(const float4*)&Bs[kk][tx * TN];
        float4 b1 = *(const float4*)&Bs[kk][tx * TN + 4];
        float a[TM] = {a0.x, a0.y, a0.z, a0.w, a1.x, a1.y, a1.z, a1.w};
        float b[TN] = {b0.x, b0.y, b0.z, b0.w, b1.x, b1.y, b1.z, b1.w};
#pragma unroll
        for (int i = 0; i < TM; ++i)
#pragma unroll
            for (int j = 0; j < TN; ++j)
                acc[i][j] = fmaf(a[i], b[j], acc[i][j]);
    }
}

// ---------------------------------------------------------------------------
// Kernel 1: projections. Y[proj][b][o][p] = sum_c W[o][c] * x[b][c][p]
// grid: (P/BN=16, COUT/BM=8, 3*B=24)
// ---------------------------------------------------------------------------
__global__ void proj_gemm(const float* __restrict__ x,
                          const float* __restrict__ Wq,
                          const float* __restrict__ Wk,
                          const float* __restrict__ Wv) {
    __shared__ __align__(16) float As[BK][LDS_];
    __shared__ __align__(16) float Bs[BK][LDS_];
    const int tid = threadIdx.x;
    const int tx = tid & 15, ty = tid >> 4;
    const int z = blockIdx.z;
    const int proj = z >> 3, b = z & 7;
    const float* W = (proj == 0) ? Wq : (proj == 1 ? Wk : Wv);
    const float* xb = x + (size_t)b * CIN * P_;
    const int m0 = blockIdx.y * BM, n0 = blockIdx.x * BN;

    const int ar = tid >> 1, ag = (tid & 1) * 4;   // A (W, row-major MxK): transpose-on-load
    const int br = tid >> 5, bc = (tid & 31) * 4;  // B (x, row-major KxN): direct

    float acc[TM][TN] = {};
    for (int kt = 0; kt < CIN; kt += BK) {
        float4 av = *(const float4*)&W[(size_t)(m0 + ar) * CIN + kt + ag];
        float4 bv = *(const float4*)&xb[(size_t)(kt + br) * P_ + n0 + bc];
        As[ag + 0][ar] = av.x; As[ag + 1][ar] = av.y;
        As[ag + 2][ar] = av.z; As[ag + 3][ar] = av.w;
        *(float4*)&Bs[br][bc] = bv;
        __syncthreads();
        micro_fma(As, Bs, acc, ty, tx);
        __syncthreads();
    }

    float* Yb = g_Y + (size_t)(proj * B_ + b) * COUT * P_;
#pragma unroll
    for (int i = 0; i < TM; ++i) {
        float* r = Yb + (size_t)(m0 + ty * TM + i) * P_ + n0 + tx * TN;
        *(float4*)&r[0] = make_float4(acc[i][0], acc[i][1], acc[i][2], acc[i][3]);
        *(float4*)&r[4] = make_float4(acc[i][4], acc[i][5], acc[i][6], acc[i][7]);
    }
}

// ---------------------------------------------------------------------------
// Kernel 2: per-channel BN stats over (batch, positions). grid: 3*COUT blocks.
// ---------------------------------------------------------------------------
__global__ void bn_stats(const float* __restrict__ gq, const float* __restrict__ bq,
                         const float* __restrict__ gk, const float* __restrict__ bk,
                         const float* __restrict__ gv, const float* __restrict__ bv) {
    const int proj = blockIdx.x >> 10, o = blockIdx.x & 1023;
    const int tid = threadIdx.x;
    const float* base = g_Y + ((size_t)(proj * B_) * COUT + o) * P_;
    float s = 0.f, s2 = 0.f;
    for (int idx = tid; idx < B_ * (P_ / 4); idx += 256) {
        int b = idx >> 9, p = (idx & 511) * 4;
        float4 v = *(const float4*)(base + (size_t)b * COUT * P_ + p);
        s  += v.x + v.y + v.z + v.w;
        s2 += v.x * v.x + v.y * v.y + v.z * v.z + v.w * v.w;
    }
    __shared__ float rs[256], rs2[256];
    rs[tid] = s; rs2[tid] = s2; __syncthreads();
    for (int st = 128; st > 0; st >>= 1) {
        if (tid < st) { rs[tid] += rs[tid + st]; rs2[tid] += rs2[tid + st]; }
        __syncthreads();
    }
    if (tid == 0) {
        const float inv = 1.f / (float)(B_ * P_);
        float mean = rs[0] * inv;
        float var = rs2[0] * inv - mean * mean;
        float rstd = rsqrtf(var + 1e-5f);
        float gg = (proj == 0) ? gq[o] : (proj == 1 ? gk[o] : gv[o]);
        float bb = (proj == 0) ? bq[o] : (proj == 1 ? bk[o] : bv[o]);
        float sc = gg * rstd;
        g_scale[proj * COUT + o] = sc;
        g_shift[proj * COUT + o] = bb - mean * sc;
    }
}

// ---------------------------------------------------------------------------
// Kernel 3: in-place BN affine + LeakyReLU(0.1) over all 3 tensors.
// ---------------------------------------------------------------------------
__global__ void bn_apply() {
    const size_t n4 = 3ull * B_ * COUT * P_ / 4;   // 12,582,912 float4
    for (size_t i = (size_t)blockIdx.x * blockDim.x + threadIdx.x; i < n4;
         i += (size_t)gridDim.x * blockDim.x) {
        size_t e = i * 4;
        int ch = (int)((e >> 11) & (COUT - 1));   // P_ = 2^11
        int proj = (int)(e >> 24);                // B_*COUT*P_ = 2^24
        float sc = g_scale[proj * COUT + ch];
        float sh = g_shift[proj * COUT + ch];
        float4 v = *((float4*)g_Y + i);
        v.x = fmaf(v.x, sc, sh); v.x = (v.x >= 0.f) ? v.x : 0.1f * v.x;
        v.y = fmaf(v.y, sc, sh); v.y = (v.y >= 0.f) ? v.y : 0.1f * v.y;
        v.z = fmaf(v.z, sc, sh); v.z = (v.z >= 0.f) ? v.z : 0.1f * v.z;
        v.w = fmaf(v.w, sc, sh); v.w = (v.w >= 0.f) ? v.w : 0.1f * v.w;
        *((float4*)g_Y + i) = v;
    }
}

// ---------------------------------------------------------------------------
// Kernel 4: scores S[z][i][j] = (1/sqrt(dh)) * sum_c K[c][i] * V[c][j]
// Both operands contiguous along M/N -> direct tile loads. grid: (16,16,64)
// ---------------------------------------------------------------------------
__global__ void score_gemm() {
    __shared__ __align__(16) float As[BK][LDS_];
    __shared__ __align__(16) float Bs[BK][LDS_];
    const int tid = threadIdx.x;
    const int tx = tid & 15, ty = tid >> 4;
    const int z = blockIdx.z;
    const int b = z >> 3, h = z & 7;
    const float* Kb = g_Y + ((size_t)(1 * B_ + b) * COUT + h * DH) * P_;
    const float* Vb = g_Y + ((size_t)(2 * B_ + b) * COUT + h * DH) * P_;
    const int m0 = blockIdx.y * BM, n0 = blockIdx.x * BN;
    const int lr = tid >> 5, lc = (tid & 31) * 4;

    float acc[TM][TN] = {};
    for (int kt = 0; kt < DH; kt += BK) {
        *(float4*)&As[lr][lc] = *(const float4*)&Kb[(size_t)(kt + lr) * P_ + m0 + lc];
        *(float4*)&Bs[lr][lc] = *(const float4*)&Vb[(size_t)(kt + lr) * P_ + n0 + lc];
        __syncthreads();
        micro_fma(As, Bs, acc, ty, tx);
        __syncthreads();
    }

    const float scale = 0.0883883476483184405f;  // 1/sqrt(128)
    float* Sb = g_S + (size_t)z * P_ * P_;
#pragma unroll
    for (int i = 0; i < TM; ++i) {
        float* r = Sb + (size_t)(m0 + ty * TM + i) * P_ + n0 + tx * TN;
        *(float4*)&r[0] = make_float4(acc[i][0] * scale, acc[i][1] * scale,
                                      acc[i][2] * scale, acc[i][3] * scale);
        *(float4*)&r[4] = make_float4(acc[i][4] * scale, acc[i][5] * scale,
                                      acc[i][6] * scale, acc[i][7] * scale);
    }
}

// ---------------------------------------------------------------------------
// Kernel 5: row softmax over j (2048). One block per row, values in registers.
// ---------------------------------------------------------------------------
__global__ void softmax_k() {
    const size_t row = blockIdx.x;
    float* ptr = g_S + row * (size_t)P_;
    const int tid = threadIdx.x;
    float4 v0 = ((float4*)ptr)[tid];
    float4 v1 = ((float4*)ptr)[tid + 256];

    float m = fmaxf(fmaxf(fmaxf(v0.x, v0.y), fmaxf(v0.z, v0.w)),
                    fmaxf(fmaxf(v1.x, v1.y), fmaxf(v1.z, v1.w)));
    __shared__ float red[256];
    red[tid] = m; __syncthreads();
    for (int st = 128; st > 0; st >>= 1) {
        if (tid < st) red[tid] = fmaxf(red[tid], red[tid + st]);
        __syncthreads();
    }
    m = red[0];
    __syncthreads();

    v0.x = __expf(v0.x - m); v0.y = __expf(v0.y - m);
    v0.z = __expf(v0.z - m); v0.w = __expf(v0.w - m);
    v1.x = __expf(v1.x - m); v1.y = __expf(v1.y - m);
    v1.z = __expf(v1.z - m); v1.w = __expf(v1.w - m);
    float s = v0.x + v0.y + v0.z + v0.w + v1.x + v1.y + v1.z + v1.w;
    red[tid] = s; __syncthreads();
    for (int st = 128; st > 0; st >>= 1) {
        if (tid < st) red[tid] += red[tid + st];
        __syncthreads();
    }
    const float inv = 1.f / red[0];
    v0.x *= inv; v0.y *= inv; v0.z *= inv; v0.w *= inv;
    v1.x *= inv; v1.y *= inv; v1.z *= inv; v1.w *= inv;
    ((float4*)ptr)[tid] = v0;
    ((float4*)ptr)[tid + 256] = v1;
}

// ---------------------------------------------------------------------------
// Kernel 6: out[b][h*DH+c][i] = sum_j S[z][i][j] * Q[c][j]
// C[i][c] tile; M = i (2048), N = c (128), K = j (2048). grid: (1,16,64)
// Both operands K-contiguous -> transpose-on-load.
// ---------------------------------------------------------------------------
__global__ void out_gemm(float* __restrict__ out) {
    __shared__ __align__(16) float As[BK][LDS_];
    __shared__ __align__(16) float Bs[BK][LDS_];
    const int tid = threadIdx.x;
    const int tx = tid & 15, ty = tid >> 4;
    const int z = blockIdx.z;
    const int b = z >> 3, h = z & 7;
    const float* A = g_S + (size_t)z * P_ * P_;                           // [i][j]
    const float* Qb = g_Y + ((size_t)(0 * B_ + b) * COUT + h * DH) * P_;  // [c][j]
    const int m0 = blockIdx.y * BM;
    const int ar = tid >> 1, ag = (tid & 1) * 4;

    float acc[TM][TN] = {};
    for (int kt = 0; kt < P_; kt += BK) {
        float4 av = *(const float4*)&A[(size_t)(m0 + ar) * P_ + kt + ag];
        float4 qv = *(const float4*)&Qb[(size_t)ar * P_ + kt + ag];
        As[ag + 0][ar] = av.x; As[ag + 1][ar] = av.y;
        As[ag + 2][ar] = av.z; As[ag + 3][ar] = av.w;
        Bs[ag + 0][ar] = qv.x; Bs[ag + 1][ar] = qv.y;
        Bs[ag + 2][ar] = qv.z; Bs[ag + 3][ar] = qv.w;
        __syncthreads();
        micro_fma(As, Bs, acc, ty, tx);
        __syncthreads();
    }

    // acc[i_local][c_local]; output contiguous along i -> vector stores per c
#pragma unroll
    for (int j = 0; j < TN; ++j) {
        int o = h * DH + tx * TN + j;
        float* r = out + ((size_t)b * COUT + o) * P_ + m0 + ty * TM;
        *(float4*)&r[0] = make_float4(acc[0][j], acc[1][j], acc[2][j], acc[3][j]);
        *(float4*)&r[4] = make_float4(acc[4][j], acc[5][j], acc[6][j], acc[7][j]);
    }
}

// ---------------------------------------------------------------------------
extern "C" void kernel_launch(void* const* d_in, const int* in_sizes, int n_in,
                              void* d_out, int out_size) {
    const float* x  = (const float*)d_in[0];
    const float* Wq = (const float*)d_in[1];
    const float* gq = (const float*)d_in[2];
    const float* bq = (const float*)d_in[3];
    const float* Wk = (const float*)d_in[4];
    const float* gk = (const float*)d_in[5];
    const float* bk = (const float*)d_in[6];
    const float* Wv = (const float*)d_in[7];
    const float* gv = (const float*)d_in[8];
    const float* bv = (const float*)d_in[9];
    float* out = (float*)d_out;

    proj_gemm<<<dim3(P_ / BN, COUT / BM, 3 * B_), 256>>>(x, Wq, Wk, Wv);
    bn_stats<<<3 * COUT, 256>>>(gq, bq, gk, bk, gv, bv);
    bn_apply<<<4096, 256>>>();
    score_gemm<<<dim3(P_ / BN, P_ / BM, B_ * H_), 256>>>();
    softmax_k<<<B_ * H_ * P_, 256>>>();
    out_gemm<<<dim3(1, P_ / BM, B_ * H_), 256>>>(out);
}

// round 9
// speedup vs baseline: 2.6459x; 2.6459x over previous
#include <cuda_runtime.h>

// Problem constants
#define B_    8
#define CIN   512
#define COUT  1024
#define P_    2048
#define H_    8
#define DH    128            // COUT / H

// GEMM tiling (tf32 mma)
#define BM 128
#define BN 128
#define BKK 16               // K tile (2 mma k-steps of 8)
#define LDMK 20              // m-major shared stride (BKK + 4)
#define LDKN 136             // k-major shared stride (BN + 8)

// Scratch (device globals: allocation-free per harness rules)
__device__ float g_Y[50331648];      // [3][B][COUT][P]  = 192 MB (Q,K,V)
__device__ float g_S[268435456];     // [B*H][P][P]      = 1 GiB  (attention map)
__device__ float g_scale[3 * COUT];
__device__ float g_shift[3 * COUT];

// ---------------------------------------------------------------------------
// tf32 helpers
// ---------------------------------------------------------------------------
__device__ __forceinline__ unsigned f2t(float f) {
    unsigned u;
    asm("cvt.rna.tf32.f32 %0, %1;" : "=r"(u) : "f"(f));
    return u;
}
__device__ __forceinline__ uint4 cvt4(float4 v) {
    return make_uint4(f2t(v.x), f2t(v.y), f2t(v.z), f2t(v.w));
}

__device__ __forceinline__ void mma8(float4& d, const unsigned a[4], const unsigned b[2]) {
    asm volatile(
        "mma.sync.aligned.m16n8k8.row.col.f32.tf32.tf32.f32 "
        "{%0,%1,%2,%3}, {%4,%5,%6,%7}, {%8,%9}, {%0,%1,%2,%3};"
        : "+f"(d.x), "+f"(d.y), "+f"(d.z), "+f"(d.w)
        : "r"(a[0]), "r"(a[1]), "r"(a[2]), "r"(a[3]), "r"(b[0]), "r"(b[1]));
}

// Fragment loaders.
// MK layout: element (m, k) at [m*LDMK + k]  (for k-contiguous globals)
// KN layout: element (k, n) at [k*LDKN + n]  (for m/n-contiguous globals)
__device__ __forceinline__ void lda_mk(unsigned a[4], const unsigned* As, int m, int k) {
    a[0] = As[m * LDMK + k];
    a[1] = As[(m + 8) * LDMK + k];
    a[2] = As[m * LDMK + k + 4];
    a[3] = As[(m + 8) * LDMK + k + 4];
}
__device__ __forceinline__ void lda_kn(unsigned a[4], const unsigned* As, int m, int k) {
    a[0] = As[k * LDKN + m];
    a[1] = As[k * LDKN + m + 8];
    a[2] = As[(k + 4) * LDKN + m];
    a[3] = As[(k + 4) * LDKN + m + 8];
}
__device__ __forceinline__ void ldb_mk(unsigned b[2], const unsigned* Bs, int n, int k) {
    b[0] = Bs[n * LDMK + k];
    b[1] = Bs[n * LDMK + k + 4];
}
__device__ __forceinline__ void ldb_kn(unsigned b[2], const unsigned* Bs, int n, int k) {
    b[0] = Bs[k * LDKN + n];
    b[1] = Bs[(k + 4) * LDKN + n];
}

// ---------------------------------------------------------------------------
// Kernel 1: projections. Y[proj][b][o][p] = sum_c W[o][c] * x[b][c][p]
// A = W [M=o][K=c] k-contig -> MK layout. B = x [K=c][N=p] n-contig -> KN.
// grid: (P/BN=16, COUT/BM=8, 3*B=24), 256 threads.
// ---------------------------------------------------------------------------
__global__ __launch_bounds__(256) void proj_gemm(const float* __restrict__ x,
                                                 const float* __restrict__ Wq,
                                                 const float* __restrict__ Wk,
                                                 const float* __restrict__ Wv) {
    __shared__ unsigned As[BM * LDMK];
    __shared__ unsigned Bs[BKK * LDKN];
    const int tid = threadIdx.x;
    const int lane = tid & 31, warp = tid >> 5;
    const int g = lane >> 2, tg = lane & 3;
    const int wm0 = (warp >> 2) * 64, wn0 = (warp & 3) * 32;
    const int z = blockIdx.z;
    const int proj = z >> 3, b = z & 7;
    const float* W = (proj == 0) ? Wq : (proj == 1 ? Wk : Wv);
    const float* xb = x + (size_t)b * CIN * P_;
    const int m0 = blockIdx.y * BM, n0 = blockIdx.x * BN;

    const int ar = tid >> 2, acg = (tid & 3) * 4;   // A staging: 2 float4/thread

    float4 acc[4][4];
#pragma unroll
    for (int i = 0; i < 4; ++i)
#pragma unroll
        for (int j = 0; j < 4; ++j) acc[i][j] = make_float4(0.f, 0.f, 0.f, 0.f);

    float4 areg[2], breg[2];
#pragma unroll
    for (int q = 0; q < 2; ++q) {
        areg[q] = *(const float4*)&W[(size_t)(m0 + ar + q * 64) * CIN + acg];
        breg[q] = *(const float4*)&xb[(size_t)(warp + q * 8) * P_ + n0 + lane * 4];
    }

    for (int kt = 0; kt < CIN; kt += BKK) {
#pragma unroll
        for (int q = 0; q < 2; ++q) {
            *(uint4*)&As[(ar + q * 64) * LDMK + acg] = cvt4(areg[q]);
            *(uint4*)&Bs[(warp + q * 8) * LDKN + lane * 4] = cvt4(breg[q]);
        }
        __syncthreads();
        if (kt + BKK < CIN) {
#pragma unroll
            for (int q = 0; q < 2; ++q) {
                areg[q] = *(const float4*)&W[(size_t)(m0 + ar + q * 64) * CIN + kt + BKK + acg];
                breg[q] = *(const float4*)&xb[(size_t)(kt + BKK + warp + q * 8) * P_ + n0 + lane * 4];
            }
        }
#pragma unroll
        for (int kb = 0; kb < BKK; kb += 8) {
            unsigned a[4][4], bb[4][2];
#pragma unroll
            for (int mf = 0; mf < 4; ++mf) lda_mk(a[mf], As, wm0 + mf * 16 + g, kb + tg);
#pragma unroll
            for (int nf = 0; nf < 4; ++nf) ldb_kn(bb[nf], Bs, wn0 + nf * 8 + g, kb + tg);
#pragma unroll
            for (int mf = 0; mf < 4; ++mf)
#pragma unroll
                for (int nf = 0; nf < 4; ++nf) mma8(acc[mf][nf], a[mf], bb[nf]);
        }
        __syncthreads();
    }

    float* Yb = g_Y + (size_t)(proj * B_ + b) * COUT * P_;
#pragma unroll
    for (int mf = 0; mf < 4; ++mf)
#pragma unroll
        for (int nf = 0; nf < 4; ++nf) {
            int row = m0 + wm0 + mf * 16 + g;
            int col = n0 + wn0 + nf * 8 + 2 * tg;
            float4 c = acc[mf][nf];
            *(float2*)&Yb[(size_t)row * P_ + col] = make_float2(c.x, c.y);
            *(float2*)&Yb[(size_t)(row + 8) * P_ + col] = make_float2(c.z, c.w);
        }
}

// ---------------------------------------------------------------------------
// Kernel 2: per-channel BN stats over (batch, positions). grid: 3*COUT blocks.
// ---------------------------------------------------------------------------
__global__ void bn_stats(const float* __restrict__ gq, const float* __restrict__ bq,
                         const float* __restrict__ gk, const float* __restrict__ bk,
                         const float* __restrict__ gv, const float* __restrict__ bv) {
    const int proj = blockIdx.x >> 10, o = blockIdx.x & 1023;
    const int tid = threadIdx.x;
    const float* base = g_Y + ((size_t)(proj * B_) * COUT + o) * P_;
    float s = 0.f, s2 = 0.f;
    for (int idx = tid; idx < B_ * (P_ / 4); idx += 256) {
        int b = idx >> 9, p = (idx & 511) * 4;
        float4 v = *(const float4*)(base + (size_t)b * COUT * P_ + p);
        s  += v.x + v.y + v.z + v.w;
        s2 += v.x * v.x + v.y * v.y + v.z * v.z + v.w * v.w;
    }
    __shared__ float rs[256], rs2[256];
    rs[tid] = s; rs2[tid] = s2; __syncthreads();
    for (int st = 128; st > 0; st >>= 1) {
        if (tid < st) { rs[tid] += rs[tid + st]; rs2[tid] += rs2[tid + st]; }
        __syncthreads();
    }
    if (tid == 0) {
        const float inv = 1.f / (float)(B_ * P_);
        float mean = rs[0] * inv;
        float var = rs2[0] * inv - mean * mean;
        float rstd = rsqrtf(var + 1e-5f);
        float gg = (proj == 0) ? gq[o] : (proj == 1 ? gk[o] : gv[o]);
        float bb = (proj == 0) ? bq[o] : (proj == 1 ? bk[o] : bv[o]);
        float sc = gg * rstd;
        g_scale[proj * COUT + o] = sc;
        g_shift[proj * COUT + o] = bb - mean * sc;
    }
}

// ---------------------------------------------------------------------------
// Kernel 3: in-place BN affine + LeakyReLU(0.1).
// ---------------------------------------------------------------------------
__global__ void bn_apply() {
    const size_t n4 = 3ull * B_ * COUT * P_ / 4;
    for (size_t i = (size_t)blockIdx.x * blockDim.x + threadIdx.x; i < n4;
         i += (size_t)gridDim.x * blockDim.x) {
        size_t e = i * 4;
        int ch = (int)((e >> 11) & (COUT - 1));
        int proj = (int)(e >> 24);
        float sc = g_scale[proj * COUT + ch];
        float sh = g_shift[proj * COUT + ch];
        float4 v = *((float4*)g_Y + i);
        v.x = fmaf(v.x, sc, sh); v.x = (v.x >= 0.f) ? v.x : 0.1f * v.x;
        v.y = fmaf(v.y, sc, sh); v.y = (v.y >= 0.f) ? v.y : 0.1f * v.y;
        v.z = fmaf(v.z, sc, sh); v.z = (v.z >= 0.f) ? v.z : 0.1f * v.z;
        v.w = fmaf(v.w, sc, sh); v.w = (v.w >= 0.f) ? v.w : 0.1f * v.w;
        *((float4*)g_Y + i) = v;
    }
}

// ---------------------------------------------------------------------------
// Kernel 4: scores S[z][i][j] = (1/sqrt(dh)) * sum_c K[c][i] * V[c][j]
// A = K [K=c][M=i] m-contig -> KN layout. B = V same -> KN. grid: (16,16,64).
// ---------------------------------------------------------------------------
__global__ __launch_bounds__(256) void score_gemm() {
    __shared__ unsigned As[BKK * LDKN];
    __shared__ unsigned Bs[BKK * LDKN];
    const int tid = threadIdx.x;
    const int lane = tid & 31, warp = tid >> 5;
    const int g = lane >> 2, tg = lane & 3;
    const int wm0 = (warp >> 2) * 64, wn0 = (warp & 3) * 32;
    const int z = blockIdx.z;
    const int b = z >> 3, h = z & 7;
    const float* Kb = g_Y + ((size_t)(1 * B_ + b) * COUT + h * DH) * P_;
    const float* Vb = g_Y + ((size_t)(2 * B_ + b) * COUT + h * DH) * P_;
    const int m0 = blockIdx.y * BM, n0 = blockIdx.x * BN;

    float4 acc[4][4];
#pragma unroll
    for (int i = 0; i < 4; ++i)
#pragma unroll
        for (int j = 0; j < 4; ++j) acc[i][j] = make_float4(0.f, 0.f, 0.f, 0.f);

    float4 areg[2], breg[2];
#pragma unroll
    for (int q = 0; q < 2; ++q) {
        areg[q] = *(const float4*)&Kb[(size_t)(warp + q * 8) * P_ + m0 + lane * 4];
        breg[q] = *(const float4*)&Vb[(size_t)(warp + q * 8) * P_ + n0 + lane * 4];
    }

    for (int kt = 0; kt < DH; kt += BKK) {
#pragma unroll
        for (int q = 0; q < 2; ++q) {
            *(uint4*)&As[(warp + q * 8) * LDKN + lane * 4] = cvt4(areg[q]);
            *(uint4*)&Bs[(warp + q * 8) * LDKN + lane * 4] = cvt4(breg[q]);
        }
        __syncthreads();
        if (kt + BKK < DH) {
#pragma unroll
            for (int q = 0; q < 2; ++q) {
                areg[q] = *(const float4*)&Kb[(size_t)(kt + BKK + warp + q * 8) * P_ + m0 + lane * 4];
                breg[q] = *(const float4*)&Vb[(size_t)(kt + BKK + warp + q * 8) * P_ + n0 + lane * 4];
            }
        }
#pragma unroll
        for (int kb = 0; kb < BKK; kb += 8) {
            unsigned a[4][4], bb[4][2];
#pragma unroll
            for (int mf = 0; mf < 4; ++mf) lda_kn(a[mf], As, wm0 + mf * 16 + g, kb + tg);
#pragma unroll
            for (int nf = 0; nf < 4; ++nf) ldb_kn(bb[nf], Bs, wn0 + nf * 8 + g, kb + tg);
#pragma unroll
            for (int mf = 0; mf < 4; ++mf)
#pragma unroll
                for (int nf = 0; nf < 4; ++nf) mma8(acc[mf][nf], a[mf], bb[nf]);
        }
        __syncthreads();
    }

    const float scale = 0.0883883476483184405f;  // 1/sqrt(128)
    float* Sb = g_S + (size_t)z * P_ * P_;
#pragma unroll
    for (int mf = 0; mf < 4; ++mf)
#pragma unroll
        for (int nf = 0; nf < 4; ++nf) {
            int row = m0 + wm0 + mf * 16 + g;
            int col = n0 + wn0 + nf * 8 + 2 * tg;
            float4 c = acc[mf][nf];
            *(float2*)&Sb[(size_t)row * P_ + col] = make_float2(c.x * scale, c.y * scale);
            *(float2*)&Sb[(size_t)(row + 8) * P_ + col] = make_float2(c.z * scale, c.w * scale);
        }
}

// ---------------------------------------------------------------------------
// Kernel 5: row softmax over j (2048). One block per row.
// ---------------------------------------------------------------------------
__global__ void softmax_k() {
    const size_t row = blockIdx.x;
    float* ptr = g_S + row * (size_t)P_;
    const int tid = threadIdx.x;
    float4 v0 = ((float4*)ptr)[tid];
    float4 v1 = ((float4*)ptr)[tid + 256];

    float m = fmaxf(fmaxf(fmaxf(v0.x, v0.y), fmaxf(v0.z, v0.w)),
                    fmaxf(fmaxf(v1.x, v1.y), fmaxf(v1.z, v1.w)));
    __shared__ float red[256];
    red[tid] = m; __syncthreads();
    for (int st = 128; st > 0; st >>= 1) {
        if (tid < st) red[tid] = fmaxf(red[tid], red[tid + st]);
        __syncthreads();
    }
    m = red[0];
    __syncthreads();

    v0.x = __expf(v0.x - m); v0.y = __expf(v0.y - m);
    v0.z = __expf(v0.z - m); v0.w = __expf(v0.w - m);
    v1.x = __expf(v1.x - m); v1.y = __expf(v1.y - m);
    v1.z = __expf(v1.z - m); v1.w = __expf(v1.w - m);
    float s = v0.x + v0.y + v0.z + v0.w + v1.x + v1.y + v1.z + v1.w;
    red[tid] = s; __syncthreads();
    for (int st = 128; st > 0; st >>= 1) {
        if (tid < st) red[tid] += red[tid + st];
        __syncthreads();
    }
    const float inv = 1.f / red[0];
    v0.x *= inv; v0.y *= inv; v0.z *= inv; v0.w *= inv;
    v1.x *= inv; v1.y *= inv; v1.z *= inv; v1.w *= inv;
    ((float4*)ptr)[tid] = v0;
    ((float4*)ptr)[tid + 256] = v1;
}

// ---------------------------------------------------------------------------
// Kernel 6: out[b][h*DH + m][i] = sum_j Q[m][j] * S[i][j]   (M=c=128, N=i, K=j)
// A = Q [M=c][K=j] k-contig -> MK. B = S [N=i][K=j] k-contig -> "NK" (MK-style).
// Output contiguous along N=i -> coalesced float2 stores. grid: (16, 1, 64).
// ---------------------------------------------------------------------------
__global__ __launch_bounds__(256) void out_gemm(float* __restrict__ out) {
    __shared__ unsigned As[BM * LDMK];
    __shared__ unsigned Bs[BN * LDMK];
    const int tid = threadIdx.x;
    const int lane = tid & 31, warp = tid >> 5;
    const int g = lane >> 2, tg = lane & 3;
    const int wm0 = (warp >> 2) * 64, wn0 = (warp & 3) * 32;
    const int z = blockIdx.z;
    const int b = z >> 3, h = z & 7;
    const float* Qb = g_Y + ((size_t)(0 * B_ + b) * COUT + h * DH) * P_;  // [c][j]
    const float* Sb = g_S + (size_t)z * P_ * P_;                          // [i][j]
    const int n0 = blockIdx.x * BN;

    const int ar = tid >> 2, acg = (tid & 3) * 4;

    float4 acc[4][4];
#pragma unroll
    for (int i = 0; i < 4; ++i)
#pragma unroll
        for (int j = 0; j < 4; ++j) acc[i][j] = make_float4(0.f, 0.f, 0.f, 0.f);

    float4 areg[2], breg[2];
#pragma unroll
    for (int q = 0; q < 2; ++q) {
        areg[q] = *(const float4*)&Qb[(size_t)(ar + q * 64) * P_ + acg];
        breg[q] = *(const float4*)&Sb[(size_t)(n0 + ar + q * 64) * P_ + acg];
    }

    for (int kt = 0; kt < P_; kt += BKK) {
#pragma unroll
        for (int q = 0; q < 2; ++q) {
            *(uint4*)&As[(ar + q * 64) * LDMK + acg] = cvt4(areg[q]);
            *(uint4*)&Bs[(ar + q * 64) * LDMK + acg] = cvt4(breg[q]);
        }
        __syncthreads();
        if (kt + BKK < P_) {
#pragma unroll
            for (int q = 0; q < 2; ++q) {
                areg[q] = *(const float4*)&Qb[(size_t)(ar + q * 64) * P_ + kt + BKK + acg];
                breg[q] = *(const float4*)&Sb[(size_t)(n0 + ar + q * 64) * P_ + kt + BKK + acg];
            }
        }
#pragma unroll
        for (int kb = 0; kb < BKK; kb += 8) {
            unsigned a[4][4], bb[4][2];
#pragma unroll
            for (int mf = 0; mf < 4; ++mf) lda_mk(a[mf], As, wm0 + mf * 16 + g, kb + tg);
#pragma unroll
            for (int nf = 0; nf < 4; ++nf) ldb_mk(bb[nf], Bs, wn0 + nf * 8 + g, kb + tg);
#pragma unroll
            for (int mf = 0; mf < 4; ++mf)
#pragma unroll
                for (int nf = 0; nf < 4; ++nf) mma8(acc[mf][nf], a[mf], bb[nf]);
        }
        __syncthreads();
    }

#pragma unroll
    for (int mf = 0; mf < 4; ++mf)
#pragma unroll
        for (int nf = 0; nf < 4; ++nf) {
            int row = wm0 + mf * 16 + g;                 // c within head
            int col = n0 + wn0 + nf * 8 + 2 * tg;        // i
            float4 c = acc[mf][nf];
            float* r0 = out + ((size_t)b * COUT + h * DH + row) * P_ + col;
            float* r1 = out + ((size_t)b * COUT + h * DH + row + 8) * P_ + col;
            *(float2*)r0 = make_float2(c.x, c.y);
            *(float2*)r1 = make_float2(c.z, c.w);
        }
}

// ---------------------------------------------------------------------------
extern "C" void kernel_launch(void* const* d_in, const int* in_sizes, int n_in,
                              void* d_out, int out_size) {
    const float* x  = (const float*)d_in[0];
    const float* Wq = (const float*)d_in[1];
    const float* gq = (const float*)d_in[2];
    const float* bq = (const float*)d_in[3];
    const float* Wk = (const float*)d_in[4];
    const float* gk = (const float*)d_in[5];
    const float* bk = (const float*)d_in[6];
    const float* Wv = (const float*)d_in[7];
    const float* gv = (const float*)d_in[8];
    const float* bv = (const float*)d_in[9];
    float* out = (float*)d_out;

    proj_gemm<<<dim3(P_ / BN, COUT / BM, 3 * B_), 256>>>(x, Wq, Wk, Wv);
    bn_stats<<<3 * COUT, 256>>>(gq, bq, gk, bk, gv, bv);
    bn_apply<<<4096, 256>>>();
    score_gemm<<<dim3(P_ / BN, P_ / BM, B_ * H_), 256>>>();
    softmax_k<<<B_ * H_ * P_, 256>>>();
    out_gemm<<<dim3(P_ / BN, 1, B_ * H_), 256>>>(out);
}

// round 12
// speedup vs baseline: 2.9501x; 1.1149x over previous
#include <cuda_runtime.h>

// Problem constants
#define B_    8
#define CIN   512
#define COUT  1024
#define P_    2048
#define H_    8
#define DH    128            // COUT / H

// GEMM tiling (tf32 mma)
#define BM 128
#define BN 128
#define BKK 16               // K tile (2 mma k-steps of 8)
#define LDMK 20              // m-major shared stride (BKK + 4)
#define LDKN 136             // k-major shared stride (BN + 8)

// Scratch (device globals: allocation-free per harness rules)
__device__ float g_Y[50331648];      // [3][B][COUT][P]  = 192 MB (Q,K,V)
__device__ float g_scale[3 * COUT];
__device__ float g_shift[3 * COUT];

// ---------------------------------------------------------------------------
// tf32 helpers
// ---------------------------------------------------------------------------
__device__ __forceinline__ unsigned f2t(float f) {
    unsigned u;
    asm("cvt.rna.tf32.f32 %0, %1;" : "=r"(u) : "f"(f));
    return u;
}
__device__ __forceinline__ uint4 cvt4(float4 v) {
    return make_uint4(f2t(v.x), f2t(v.y), f2t(v.z), f2t(v.w));
}

__device__ __forceinline__ void mma8(float4& d, const unsigned a[4], const unsigned b[2]) {
    asm volatile(
        "mma.sync.aligned.m16n8k8.row.col.f32.tf32.tf32.f32 "
        "{%0,%1,%2,%3}, {%4,%5,%6,%7}, {%8,%9}, {%0,%1,%2,%3};"
        : "+f"(d.x), "+f"(d.y), "+f"(d.z), "+f"(d.w)
        : "r"(a[0]), "r"(a[1]), "r"(a[2]), "r"(a[3]), "r"(b[0]), "r"(b[1]));
}

__device__ __forceinline__ void lda_mk(unsigned a[4], const unsigned* As, int m, int k) {
    a[0] = As[m * LDMK + k];
    a[1] = As[(m + 8) * LDMK + k];
    a[2] = As[m * LDMK + k + 4];
    a[3] = As[(m + 8) * LDMK + k + 4];
}
__device__ __forceinline__ void ldb_kn(unsigned b[2], const unsigned* Bs, int n, int k) {
    b[0] = Bs[k * LDKN + n];
    b[1] = Bs[(k + 4) * LDKN + n];
}

// ---------------------------------------------------------------------------
// Kernel 1: projections. Y[proj][b][o][p] = sum_c W[o][c] * x[b][c][p]
// ---------------------------------------------------------------------------
__global__ __launch_bounds__(256) void proj_gemm(const float* __restrict__ x,
                                                 const float* __restrict__ Wq,
                                                 const float* __restrict__ Wk,
                                                 const float* __restrict__ Wv) {
    __shared__ unsigned As[BM * LDMK];
    __shared__ unsigned Bs[BKK * LDKN];
    const int tid = threadIdx.x;
    const int lane = tid & 31, warp = tid >> 5;
    const int g = lane >> 2, tg = lane & 3;
    const int wm0 = (warp >> 2) * 64, wn0 = (warp & 3) * 32;
    const int z = blockIdx.z;
    const int proj = z >> 3, b = z & 7;
    const float* W = (proj == 0) ? Wq : (proj == 1 ? Wk : Wv);
    const float* xb = x + (size_t)b * CIN * P_;
    const int m0 = blockIdx.y * BM, n0 = blockIdx.x * BN;

    const int ar = tid >> 2, acg = (tid & 3) * 4;

    float4 acc[4][4];
#pragma unroll
    for (int i = 0; i < 4; ++i)
#pragma unroll
        for (int j = 0; j < 4; ++j) acc[i][j] = make_float4(0.f, 0.f, 0.f, 0.f);

    float4 areg[2], breg[2];
#pragma unroll
    for (int q = 0; q < 2; ++q) {
        areg[q] = *(const float4*)&W[(size_t)(m0 + ar + q * 64) * CIN + acg];
        breg[q] = *(const float4*)&xb[(size_t)(warp + q * 8) * P_ + n0 + lane * 4];
    }

    for (int kt = 0; kt < CIN; kt += BKK) {
#pragma unroll
        for (int q = 0; q < 2; ++q) {
            *(uint4*)&As[(ar + q * 64) * LDMK + acg] = cvt4(areg[q]);
            *(uint4*)&Bs[(warp + q * 8) * LDKN + lane * 4] = cvt4(breg[q]);
        }
        __syncthreads();
        if (kt + BKK < CIN) {
#pragma unroll
            for (int q = 0; q < 2; ++q) {
                areg[q] = *(const float4*)&W[(size_t)(m0 + ar + q * 64) * CIN + kt + BKK + acg];
                breg[q] = *(const float4*)&xb[(size_t)(kt + BKK + warp + q * 8) * P_ + n0 + lane * 4];
            }
        }
#pragma unroll
        for (int kb = 0; kb < BKK; kb += 8) {
            unsigned a[4][4], bb[4][2];
#pragma unroll
            for (int mf = 0; mf < 4; ++mf) lda_mk(a[mf], As, wm0 + mf * 16 + g, kb + tg);
#pragma unroll
            for (int nf = 0; nf < 4; ++nf) ldb_kn(bb[nf], Bs, wn0 + nf * 8 + g, kb + tg);
#pragma unroll
            for (int mf = 0; mf < 4; ++mf)
#pragma unroll
                for (int nf = 0; nf < 4; ++nf) mma8(acc[mf][nf], a[mf], bb[nf]);
        }
        __syncthreads();
    }

    float* Yb = g_Y + (size_t)(proj * B_ + b) * COUT * P_;
#pragma unroll
    for (int mf = 0; mf < 4; ++mf)
#pragma unroll
        for (int nf = 0; nf < 4; ++nf) {
            int row = m0 + wm0 + mf * 16 + g;
            int col = n0 + wn0 + nf * 8 + 2 * tg;
            float4 c = acc[mf][nf];
            *(float2*)&Yb[(size_t)row * P_ + col] = make_float2(c.x, c.y);
            *(float2*)&Yb[(size_t)(row + 8) * P_ + col] = make_float2(c.z, c.w);
        }
}

// ---------------------------------------------------------------------------
// Kernel 2: per-channel BN stats. grid: 3*COUT blocks.
// ---------------------------------------------------------------------------
__global__ void bn_stats(const float* __restrict__ gq, const float* __restrict__ bq,
                         const float* __restrict__ gk, const float* __restrict__ bk,
                         const float* __restrict__ gv, const float* __restrict__ bv) {
    const int proj = blockIdx.x >> 10, o = blockIdx.x & 1023;
    const int tid = threadIdx.x;
    const float* base = g_Y + ((size_t)(proj * B_) * COUT + o) * P_;
    float s = 0.f, s2 = 0.f;
    for (int idx = tid; idx < B_ * (P_ / 4); idx += 256) {
        int b = idx >> 9, p = (idx & 511) * 4;
        float4 v = *(const float4*)(base + (size_t)b * COUT * P_ + p);
        s  += v.x + v.y + v.z + v.w;
        s2 += v.x * v.x + v.y * v.y + v.z * v.z + v.w * v.w;
    }
    __shared__ float rs[256], rs2[256];
    rs[tid] = s; rs2[tid] = s2; __syncthreads();
    for (int st = 128; st > 0; st >>= 1) {
        if (tid < st) { rs[tid] += rs[tid + st]; rs2[tid] += rs2[tid + st]; }
        __syncthreads();
    }
    if (tid == 0) {
        const float inv = 1.f / (float)(B_ * P_);
        float mean = rs[0] * inv;
        float var = rs2[0] * inv - mean * mean;
        float rstd = rsqrtf(var + 1e-5f);
        float gg = (proj == 0) ? gq[o] : (proj == 1 ? gk[o] : gv[o]);
        float bb = (proj == 0) ? bq[o] : (proj == 1 ? bk[o] : bv[o]);
        float sc = gg * rstd;
        g_scale[proj * COUT + o] = sc;
        g_shift[proj * COUT + o] = bb - mean * sc;
    }
}

// ---------------------------------------------------------------------------
// Kernel 3: in-place BN affine + LeakyReLU(0.1).
// ---------------------------------------------------------------------------
__global__ void bn_apply() {
    const size_t n4 = 3ull * B_ * COUT * P_ / 4;
    for (size_t i = (size_t)blockIdx.x * blockDim.x + threadIdx.x; i < n4;
         i += (size_t)gridDim.x * blockDim.x) {
        size_t e = i * 4;
        int ch = (int)((e >> 11) & (COUT - 1));
        int proj = (int)(e >> 24);
        float sc = g_scale[proj * COUT + ch];
        float sh = g_shift[proj * COUT + ch];
        float4 v = *((float4*)g_Y + i);
        v.x = fmaf(v.x, sc, sh); v.x = (v.x >= 0.f) ? v.x : 0.1f * v.x;
        v.y = fmaf(v.y, sc, sh); v.y = (v.y >= 0.f) ? v.y : 0.1f * v.y;
        v.z = fmaf(v.z, sc, sh); v.z = (v.z >= 0.f) ? v.z : 0.1f * v.z;
        v.w = fmaf(v.w, sc, sh); v.w = (v.w >= 0.f) ? v.w : 0.1f * v.w;
        *((float4*)g_Y + i) = v;
    }
}

// ---------------------------------------------------------------------------
// Kernel 4: FUSED attention. One CTA per (z, i-block of 128 rows).
//   S[i][j] = (1/sqrt(dh)) * sum_c K[c][i] V[c][j]      (K resident in smem)
//   P = exp(S)  (no max-subtraction: scores bounded; fp32 sum safe)
//   out[c][i] = (sum_j P[i][j] Q[c][j]) / (sum_j P[i][j])
// grid: (16 i-blocks, 1, 64 z), 256 threads, ~210.5 KB dynamic smem.
//
// Shared layout (word offsets):
//   Ks [128 c][136]  KN:  Ks[c*136 + i_loc]           69632 B
//   Ps [128 i][132]  MK:  Ps[i_loc*132 + j_loc]       67584 B
//   Qs [128 c][132]  MK:  Qs[c*132 + j_loc]           67584 B
//   Vs [ 16 c][136]  KN staging                        8704 B
//   red[4 wn][128 rows] fp32 row-sum reduction         2048 B
// ---------------------------------------------------------------------------
#define KS_OFF   0
#define PS_OFF   (128 * 136)
#define QS_OFF   (PS_OFF + 128 * 132)
#define VS_OFF   (QS_OFF + 128 * 132)
#define RED_OFF  (VS_OFF + 16 * 136)
#define SMEM_WORDS (RED_OFF + 4 * 128)   // 53888 words = 215552 bytes

__global__ __launch_bounds__(256, 1) void attn_fused(float* __restrict__ out) {
    extern __shared__ unsigned sm[];
    unsigned* Ks = sm + KS_OFF;
    unsigned* Ps = sm + PS_OFF;
    unsigned* Qs = sm + QS_OFF;
    unsigned* Vs = sm + VS_OFF;
    float*   red = (float*)(sm + RED_OFF);

    const int tid = threadIdx.x;
    const int lane = tid & 31, warp = tid >> 5;
    const int g = lane >> 2, tg = lane & 3;
    const int wm0 = (warp >> 2) * 64, wn0 = (warp & 3) * 32;
    const int wn = warp & 3;
    const int z = blockIdx.y;
    const int b = z >> 3, h = z & 7;
    const int m0 = blockIdx.x * BM;   // i-block origin

    const float* Qg = g_Y + ((size_t)(0 * B_ + b) * COUT + h * DH) * P_;  // [c][p]
    const float* Kg = g_Y + ((size_t)(1 * B_ + b) * COUT + h * DH) * P_;
    const float* Vg = g_Y + ((size_t)(2 * B_ + b) * COUT + h * DH) * P_;

    // --- Load K tile (resident): Ks[c][i_loc], tf32 ---
#pragma unroll
    for (int q = 0; q < 16; ++q) {
        int c = q * 8 + warp;
        float4 v = *(const float4*)&Kg[(size_t)c * P_ + m0 + lane * 4];
        *(uint4*)&Ks[c * 136 + lane * 4] = cvt4(v);
    }
    __syncthreads();

    float4 acc2[4][4];
    float  lsum[4][2];
#pragma unroll
    for (int i = 0; i < 4; ++i) {
        lsum[i][0] = 0.f; lsum[i][1] = 0.f;
#pragma unroll
        for (int j = 0; j < 4; ++j) acc2[i][j] = make_float4(0.f, 0.f, 0.f, 0.f);
    }

    const float scale = 0.0883883476483184405f;  // 1/sqrt(128)

    for (int jt = 0; jt < 16; ++jt) {
        const int j0 = jt * 128;

        // ---- mma1: S tile = K^T V over c ----
        float4 acc1[4][4];
#pragma unroll
        for (int i = 0; i < 4; ++i)
#pragma unroll
            for (int j = 0; j < 4; ++j) acc1[i][j] = make_float4(0.f, 0.f, 0.f, 0.f);

        float4 vr0 = *(const float4*)&Vg[(size_t)warp * P_ + j0 + lane * 4];
        float4 vr1 = *(const float4*)&Vg[(size_t)(8 + warp) * P_ + j0 + lane * 4];

        for (int ct = 0; ct < DH; ct += 16) {
            *(uint4*)&Vs[warp * 136 + lane * 4] = cvt4(vr0);
            *(uint4*)&Vs[(warp + 8) * 136 + lane * 4] = cvt4(vr1);
            __syncthreads();
            if (ct + 16 < DH) {
                vr0 = *(const float4*)&Vg[(size_t)(ct + 16 + warp) * P_ + j0 + lane * 4];
                vr1 = *(const float4*)&Vg[(size_t)(ct + 24 + warp) * P_ + j0 + lane * 4];
            }
#pragma unroll
            for (int kb = 0; kb < 16; kb += 8) {
                const int ka = ct + kb + tg;   // absolute c for Ks
                const int kl = kb + tg;        // local c for Vs
                unsigned a[4][4], bb[4][2];
#pragma unroll
                for (int mf = 0; mf < 4; ++mf) {
                    int m = wm0 + mf * 16 + g;
                    a[mf][0] = Ks[ka * 136 + m];
                    a[mf][1] = Ks[ka * 136 + m + 8];
                    a[mf][2] = Ks[(ka + 4) * 136 + m];
                    a[mf][3] = Ks[(ka + 4) * 136 + m + 8];
                }
#pragma unroll
                for (int nf = 0; nf < 4; ++nf) {
                    int n = wn0 + nf * 8 + g;
                    bb[nf][0] = Vs[kl * 136 + n];
                    bb[nf][1] = Vs[(kl + 4) * 136 + n];
                }
#pragma unroll
                for (int mf = 0; mf < 4; ++mf)
#pragma unroll
                    for (int nf = 0; nf < 4; ++nf) mma8(acc1[mf][nf], a[mf], bb[nf]);
            }
            __syncthreads();
        }

        // ---- Load Q tile for this j-block (overlaps with exp below) ----
#pragma unroll
        for (int q = 0; q < 16; ++q) {
            int c = q * 8 + warp;
            float4 v = *(const float4*)&Qg[(size_t)c * P_ + j0 + lane * 4];
            *(uint4*)&Qs[c * 132 + lane * 4] = cvt4(v);
        }

        // ---- exp + row-sum partials + store P (tf32) ----
#pragma unroll
        for (int mf = 0; mf < 4; ++mf) {
            int r = wm0 + mf * 16 + g;
#pragma unroll
            for (int nf = 0; nf < 4; ++nf) {
                int col = wn0 + nf * 8 + 2 * tg;
                float4 s = acc1[mf][nf];
                float px = __expf(s.x * scale);
                float py = __expf(s.y * scale);
                float pz = __expf(s.z * scale);
                float pw = __expf(s.w * scale);
                lsum[mf][0] += px + py;
                lsum[mf][1] += pz + pw;
                *(uint2*)&Ps[r * 132 + col]       = make_uint2(f2t(px), f2t(py));
                *(uint2*)&Ps[(r + 8) * 132 + col] = make_uint2(f2t(pz), f2t(pw));
            }
        }
        __syncthreads();

        // ---- mma2: acc2[i][c] += P[i][j] * Q[c][j] over this j-tile ----
#pragma unroll
        for (int kb = 0; kb < 128; kb += 8) {
            const int k = kb + tg;
            unsigned a[4][4], bb[4][2];
#pragma unroll
            for (int mf = 0; mf < 4; ++mf) {
                int m = wm0 + mf * 16 + g;
                a[mf][0] = Ps[m * 132 + k];
                a[mf][1] = Ps[(m + 8) * 132 + k];
                a[mf][2] = Ps[m * 132 + k + 4];
                a[mf][3] = Ps[(m + 8) * 132 + k + 4];
            }
#pragma unroll
            for (int nf = 0; nf < 4; ++nf) {
                int n = wn0 + nf * 8 + g;
                bb[nf][0] = Qs[n * 132 + k];
                bb[nf][1] = Qs[n * 132 + k + 4];
            }
#pragma unroll
            for (int mf = 0; mf < 4; ++mf)
#pragma unroll
                for (int nf = 0; nf < 4; ++nf) mma8(acc2[mf][nf], a[mf], bb[nf]);
        }
        __syncthreads();
    }

    // ---- Row-sum reduction: tg-quad shuffle, then across 4 n-warps ----
#pragma unroll
    for (int mf = 0; mf < 4; ++mf)
#pragma unroll
        for (int hh = 0; hh < 2; ++hh) {
            float v = lsum[mf][hh];
            v += __shfl_xor_sync(0xffffffff, v, 1);
            v += __shfl_xor_sync(0xffffffff, v, 2);
            lsum[mf][hh] = v;
        }
    if (tg == 0) {
#pragma unroll
        for (int mf = 0; mf < 4; ++mf) {
            int r = wm0 + mf * 16 + g;
            red[wn * 128 + r]     = lsum[mf][0];
            red[wn * 128 + r + 8] = lsum[mf][1];
        }
    }
    __syncthreads();

    // ---- Normalize and write out[b][h*DH + c][i] ----
#pragma unroll
    for (int mf = 0; mf < 4; ++mf) {
        int r = wm0 + mf * 16 + g;
        float inv0 = 1.f / (red[r] + red[128 + r] + red[256 + r] + red[384 + r]);
        float inv1 = 1.f / (red[r + 8] + red[128 + r + 8] + red[256 + r + 8] + red[384 + r + 8]);
        int i0 = m0 + r;
#pragma unroll
        for (int nf = 0; nf < 4; ++nf) {
            int c = wn0 + nf * 8 + 2 * tg;
            float4 v = acc2[mf][nf];
            float* o0 = out + ((size_t)b * COUT + h * DH + c) * P_;
            float* o1 = out + ((size_t)b * COUT + h * DH + c + 1) * P_;
            o0[i0]     = v.x * inv0;
            o1[i0]     = v.y * inv0;
            o0[i0 + 8] = v.z * inv1;
            o1[i0 + 8] = v.w * inv1;
        }
    }
}

// ---------------------------------------------------------------------------
extern "C" void kernel_launch(void* const* d_in, const int* in_sizes, int n_in,
                              void* d_out, int out_size) {
    const float* x  = (const float*)d_in[0];
    const float* Wq = (const float*)d_in[1];
    const float* gq = (const float*)d_in[2];
    const float* bq = (const float*)d_in[3];
    const float* Wk = (const float*)d_in[4];
    const float* gk = (const float*)d_in[5];
    const float* bk = (const float*)d_in[6];
    const float* Wv = (const float*)d_in[7];
    const float* gv = (const float*)d_in[8];
    const float* bv = (const float*)d_in[9];
    float* out = (float*)d_out;

    static int smem_set = 0;
    if (!smem_set) {
        cudaFuncSetAttribute(attn_fused, cudaFuncAttributeMaxDynamicSharedMemorySize,
                             SMEM_WORDS * 4);
        smem_set = 1;
    }

    proj_gemm<<<dim3(P_ / BN, COUT / BM, 3 * B_), 256>>>(x, Wq, Wk, Wv);
    bn_stats<<<3 * COUT, 256>>>(gq, bq, gk, bk, gv, bv);
    bn_apply<<<4096, 256>>>();
    attn_fused<<<dim3(P_ / BM, B_ * H_), 256, SMEM_WORDS * 4>>>(out);
}

// round 14
// speedup vs baseline: 4.9359x; 1.6731x over previous
#include <cuda_runtime.h>
#include <cuda_bf16.h>

// Problem constants
#define B_    8
#define CIN   512
#define COUT  1024
#define P_    2048
#define H_    8
#define DH    128            // COUT / H

// proj GEMM tiling (tf32 mma, unchanged)
#define BM 128
#define BN 128
#define BKK 16
#define LDMK 20
#define LDKN 136

// Scratch (device globals: allocation-free per harness rules)
__device__ float g_Y[50331648];      // [3][B][COUT][P]  = 192 MB (pre-BN Q,K,V)
__device__ float g_scale[3 * COUT];
__device__ float g_shift[3 * COUT];

// ---------------------------------------------------------------------------
// helpers
// ---------------------------------------------------------------------------
__device__ __forceinline__ unsigned f2t(float f) {
    unsigned u;
    asm("cvt.rna.tf32.f32 %0, %1;" : "=r"(u) : "f"(f));
    return u;
}
__device__ __forceinline__ uint4 cvt4(float4 v) {
    return make_uint4(f2t(v.x), f2t(v.y), f2t(v.z), f2t(v.w));
}

__device__ __forceinline__ void mma8(float4& d, const unsigned a[4], const unsigned b[2]) {
    asm volatile(
        "mma.sync.aligned.m16n8k8.row.col.f32.tf32.tf32.f32 "
        "{%0,%1,%2,%3}, {%4,%5,%6,%7}, {%8,%9}, {%0,%1,%2,%3};"
        : "+f"(d.x), "+f"(d.y), "+f"(d.z), "+f"(d.w)
        : "r"(a[0]), "r"(a[1]), "r"(a[2]), "r"(a[3]), "r"(b[0]), "r"(b[1]));
}

// bf16 mma m16n8k16 (each .b32 operand = bf16x2 along k)
__device__ __forceinline__ void mma16(float4& d, const unsigned a[4], const unsigned b[2]) {
    asm volatile(
        "mma.sync.aligned.m16n8k16.row.col.f32.bf16.bf16.f32 "
        "{%0,%1,%2,%3}, {%4,%5,%6,%7}, {%8,%9}, {%0,%1,%2,%3};"
        : "+f"(d.x), "+f"(d.y), "+f"(d.z), "+f"(d.w)
        : "r"(a[0]), "r"(a[1]), "r"(a[2]), "r"(a[3]), "r"(b[0]), "r"(b[1]));
}

__device__ __forceinline__ unsigned packbf(float lo, float hi) {
    __nv_bfloat162 t;
    t.x = __float2bfloat16(lo);
    t.y = __float2bfloat16(hi);
    return *(unsigned*)&t;
}
__device__ __forceinline__ float bnl(float y, float sc, float sh) {
    float v = fmaf(y, sc, sh);
    return (v >= 0.f) ? v : 0.1f * v;
}

__device__ __forceinline__ void lda_mk(unsigned a[4], const unsigned* As, int m, int k) {
    a[0] = As[m * LDMK + k];
    a[1] = As[(m + 8) * LDMK + k];
    a[2] = As[m * LDMK + k + 4];
    a[3] = As[(m + 8) * LDMK + k + 4];
}
__device__ __forceinline__ void ldb_kn(unsigned b[2], const unsigned* Bs, int n, int k) {
    b[0] = Bs[k * LDKN + n];
    b[1] = Bs[(k + 4) * LDKN + n];
}

// ---------------------------------------------------------------------------
// Kernel 1: projections (tf32). Y[proj][b][o][p] = sum_c W[o][c] * x[b][c][p]
// ---------------------------------------------------------------------------
__global__ __launch_bounds__(256) void proj_gemm(const float* __restrict__ x,
                                                 const float* __restrict__ Wq,
                                                 const float* __restrict__ Wk,
                                                 const float* __restrict__ Wv) {
    __shared__ unsigned As[BM * LDMK];
    __shared__ unsigned Bs[BKK * LDKN];
    const int tid = threadIdx.x;
    const int lane = tid & 31, warp = tid >> 5;
    const int g = lane >> 2, tg = lane & 3;
    const int wm0 = (warp >> 2) * 64, wn0 = (warp & 3) * 32;
    const int z = blockIdx.z;
    const int proj = z >> 3, b = z & 7;
    const float* W = (proj == 0) ? Wq : (proj == 1 ? Wk : Wv);
    const float* xb = x + (size_t)b * CIN * P_;
    const int m0 = blockIdx.y * BM, n0 = blockIdx.x * BN;

    const int ar = tid >> 2, acg = (tid & 3) * 4;

    float4 acc[4][4];
#pragma unroll
    for (int i = 0; i < 4; ++i)
#pragma unroll
        for (int j = 0; j < 4; ++j) acc[i][j] = make_float4(0.f, 0.f, 0.f, 0.f);

    float4 areg[2], breg[2];
#pragma unroll
    for (int q = 0; q < 2; ++q) {
        areg[q] = *(const float4*)&W[(size_t)(m0 + ar + q * 64) * CIN + acg];
        breg[q] = *(const float4*)&xb[(size_t)(warp + q * 8) * P_ + n0 + lane * 4];
    }

    for (int kt = 0; kt < CIN; kt += BKK) {
#pragma unroll
        for (int q = 0; q < 2; ++q) {
            *(uint4*)&As[(ar + q * 64) * LDMK + acg] = cvt4(areg[q]);
            *(uint4*)&Bs[(warp + q * 8) * LDKN + lane * 4] = cvt4(breg[q]);
        }
        __syncthreads();
        if (kt + BKK < CIN) {
#pragma unroll
            for (int q = 0; q < 2; ++q) {
                areg[q] = *(const float4*)&W[(size_t)(m0 + ar + q * 64) * CIN + kt + BKK + acg];
                breg[q] = *(const float4*)&xb[(size_t)(kt + BKK + warp + q * 8) * P_ + n0 + lane * 4];
            }
        }
#pragma unroll
        for (int kb = 0; kb < BKK; kb += 8) {
            unsigned a[4][4], bb[4][2];
#pragma unroll
            for (int mf = 0; mf < 4; ++mf) lda_mk(a[mf], As, wm0 + mf * 16 + g, kb + tg);
#pragma unroll
            for (int nf = 0; nf < 4; ++nf) ldb_kn(bb[nf], Bs, wn0 + nf * 8 + g, kb + tg);
#pragma unroll
            for (int mf = 0; mf < 4; ++mf)
#pragma unroll
                for (int nf = 0; nf < 4; ++nf) mma8(acc[mf][nf], a[mf], bb[nf]);
        }
        __syncthreads();
    }

    float* Yb = g_Y + (size_t)(proj * B_ + b) * COUT * P_;
#pragma unroll
    for (int mf = 0; mf < 4; ++mf)
#pragma unroll
        for (int nf = 0; nf < 4; ++nf) {
            int row = m0 + wm0 + mf * 16 + g;
            int col = n0 + wn0 + nf * 8 + 2 * tg;
            float4 c = acc[mf][nf];
            *(float2*)&Yb[(size_t)row * P_ + col] = make_float2(c.x, c.y);
            *(float2*)&Yb[(size_t)(row + 8) * P_ + col] = make_float2(c.z, c.w);
        }
}

// ---------------------------------------------------------------------------
// Kernel 2: per-channel BN stats (on pre-activation y). grid: 3*COUT blocks.
// ---------------------------------------------------------------------------
__global__ void bn_stats(const float* __restrict__ gq, const float* __restrict__ bq,
                         const float* __restrict__ gk, const float* __restrict__ bk,
                         const float* __restrict__ gv, const float* __restrict__ bv) {
    const int proj = blockIdx.x >> 10, o = blockIdx.x & 1023;
    const int tid = threadIdx.x;
    const float* base = g_Y + ((size_t)(proj * B_) * COUT + o) * P_;
    float s = 0.f, s2 = 0.f;
    for (int idx = tid; idx < B_ * (P_ / 4); idx += 256) {
        int b = idx >> 9, p = (idx & 511) * 4;
        float4 v = *(const float4*)(base + (size_t)b * COUT * P_ + p);
        s  += v.x + v.y + v.z + v.w;
        s2 += v.x * v.x + v.y * v.y + v.z * v.z + v.w * v.w;
    }
    __shared__ float rs[256], rs2[256];
    rs[tid] = s; rs2[tid] = s2; __syncthreads();
    for (int st = 128; st > 0; st >>= 1) {
        if (tid < st) { rs[tid] += rs[tid + st]; rs2[tid] += rs2[tid + st]; }
        __syncthreads();
    }
    if (tid == 0) {
        const float inv = 1.f / (float)(B_ * P_);
        float mean = rs[0] * inv;
        float var = rs2[0] * inv - mean * mean;
        float rstd = rsqrtf(var + 1e-5f);
        float gg = (proj == 0) ? gq[o] : (proj == 1 ? gk[o] : gv[o]);
        float bb = (proj == 0) ? bq[o] : (proj == 1 ? bk[o] : bv[o]);
        float sc = gg * rstd;
        g_scale[proj * COUT + o] = sc;
        g_shift[proj * COUT + o] = bb - mean * sc;
    }
}

// ---------------------------------------------------------------------------
// Kernel 3: FUSED attention, bf16 mma.m16n8k16. One CTA per (z, i-block).
// BN affine + LeakyReLU applied at staging (bn_apply kernel eliminated).
//
// Shared layout (32-bit word offsets). All words are bf16x2 paired along k:
//   Ksw [64 cw][136]  word(cw,i) = (K[2cw][i], K[2cw+1][i])      34816 B
//   Vsw [64 cw][136]  word(cw,j) = (V[2cw][j], V[2cw+1][j])      34816 B
//   Psw [64 jw][136]  word(jw,i) = (P[i][2jw], P[i][2jw+1])      34816 B
//   Qsw [128 c][68]   word(c,jw) = (Q[c][2jw], Q[c][2jw+1])      34816 B
//   red [4][128]      fp32 row-sum reduction                      2048 B
// Fragment-load bank maps: stride 136 -> 8*tg+g ; stride 68 -> 4*g+tg (bijective).
// ---------------------------------------------------------------------------
#define LDW  136
#define LDQW 68
#define AKS_OFF  0
#define AVS_OFF  (64 * LDW)
#define APS_OFF  (AVS_OFF + 64 * LDW)
#define AQS_OFF  (APS_OFF + 64 * LDW)
#define ARED_OFF (AQS_OFF + 128 * LDQW)
#define ASMEM_WORDS (ARED_OFF + 4 * 128)   // 35328 words = 141312 B

__global__ __launch_bounds__(256, 1) void attn_fused(float* __restrict__ out) {
    extern __shared__ unsigned sm[];
    unsigned* Ksw = sm + AKS_OFF;
    unsigned* Vsw = sm + AVS_OFF;
    unsigned* Psw = sm + APS_OFF;
    unsigned* Qsw = sm + AQS_OFF;
    float*    red = (float*)(sm + ARED_OFF);

    const int tid = threadIdx.x;
    const int lane = tid & 31, warp = tid >> 5;
    const int g = lane >> 2, tg = lane & 3;
    const int wm0 = (warp >> 2) * 64, wn0 = (warp & 3) * 32;
    const int wn = warp & 3;
    const int z = blockIdx.y;
    const int b = z >> 3, h = z & 7;
    const int m0 = blockIdx.x * 128;   // i-block origin

    const float* Qg = g_Y + ((size_t)(0 * B_ + b) * COUT + h * DH) * P_;  // [c][p]
    const float* Kg = g_Y + ((size_t)(1 * B_ + b) * COUT + h * DH) * P_;
    const float* Vg = g_Y + ((size_t)(2 * B_ + b) * COUT + h * DH) * P_;
    const float* scQ = g_scale + 0 * COUT + h * DH;
    const float* shQ = g_shift + 0 * COUT + h * DH;
    const float* scK = g_scale + 1 * COUT + h * DH;
    const float* shK = g_shift + 1 * COUT + h * DH;
    const float* scV = g_scale + 2 * COUT + h * DH;
    const float* shV = g_shift + 2 * COUT + h * DH;

    // --- Stage K tile (resident): pairs of c-rows interleaved into words ---
#pragma unroll
    for (int q = 0; q < 8; ++q) {
        int cw = q * 8 + warp;
        float4 r0 = *(const float4*)&Kg[(size_t)(2 * cw) * P_ + m0 + lane * 4];
        float4 r1 = *(const float4*)&Kg[(size_t)(2 * cw + 1) * P_ + m0 + lane * 4];
        float s0 = scK[2 * cw], h0 = shK[2 * cw];
        float s1 = scK[2 * cw + 1], h1 = shK[2 * cw + 1];
        uint4 w;
        w.x = packbf(bnl(r0.x, s0, h0), bnl(r1.x, s1, h1));
        w.y = packbf(bnl(r0.y, s0, h0), bnl(r1.y, s1, h1));
        w.z = packbf(bnl(r0.z, s0, h0), bnl(r1.z, s1, h1));
        w.w = packbf(bnl(r0.w, s0, h0), bnl(r1.w, s1, h1));
        *(uint4*)&Ksw[cw * LDW + lane * 4] = w;
    }
    __syncthreads();

    float4 acc2[4][4];
    float  lsum[4][2];
#pragma unroll
    for (int i = 0; i < 4; ++i) {
        lsum[i][0] = 0.f; lsum[i][1] = 0.f;
#pragma unroll
        for (int j = 0; j < 4; ++j) acc2[i][j] = make_float4(0.f, 0.f, 0.f, 0.f);
    }

    const float scale = 0.0883883476483184405f;  // 1/sqrt(128)

    for (int jt = 0; jt < 16; ++jt) {
        const int j0 = jt * 128;

        // ---- Stage V j-tile (paired c-rows) ----
#pragma unroll
        for (int q = 0; q < 8; ++q) {
            int cw = q * 8 + warp;
            float4 r0 = *(const float4*)&Vg[(size_t)(2 * cw) * P_ + j0 + lane * 4];
            float4 r1 = *(const float4*)&Vg[(size_t)(2 * cw + 1) * P_ + j0 + lane * 4];
            float s0 = scV[2 * cw], h0 = shV[2 * cw];
            float s1 = scV[2 * cw + 1], h1 = shV[2 * cw + 1];
            uint4 w;
            w.x = packbf(bnl(r0.x, s0, h0), bnl(r1.x, s1, h1));
            w.y = packbf(bnl(r0.y, s0, h0), bnl(r1.y, s1, h1));
            w.z = packbf(bnl(r0.z, s0, h0), bnl(r1.z, s1, h1));
            w.w = packbf(bnl(r0.w, s0, h0), bnl(r1.w, s1, h1));
            *(uint4*)&Vsw[cw * LDW + lane * 4] = w;
        }
        // ---- Stage Q j-tile: word(c, jw) = adjacent j pair of one row ----
#pragma unroll
        for (int q = 0; q < 16; ++q) {
            int c = q * 8 + warp;
            float4 v = *(const float4*)&Qg[(size_t)c * P_ + j0 + lane * 4];
            float s0 = scQ[c], h0 = shQ[c];
            uint2 w;
            w.x = packbf(bnl(v.x, s0, h0), bnl(v.y, s0, h0));
            w.y = packbf(bnl(v.z, s0, h0), bnl(v.w, s0, h0));
            *(uint2*)&Qsw[c * LDQW + lane * 2] = w;
        }
        __syncthreads();

        // ---- mma1: S[i][j] = sum_c K[c][i] V[c][j], 8 k16-steps over c ----
        float4 acc1[4][4];
#pragma unroll
        for (int i = 0; i < 4; ++i)
#pragma unroll
            for (int j = 0; j < 4; ++j) acc1[i][j] = make_float4(0.f, 0.f, 0.f, 0.f);

#pragma unroll
        for (int ks = 0; ks < 8; ++ks) {
            const int kw0 = ks * 8;
            unsigned a[4][4], bb[4][2];
#pragma unroll
            for (int mf = 0; mf < 4; ++mf) {
                int m = wm0 + mf * 16 + g;
                a[mf][0] = Ksw[(kw0 + tg) * LDW + m];
                a[mf][1] = Ksw[(kw0 + tg) * LDW + m + 8];
                a[mf][2] = Ksw[(kw0 + tg + 4) * LDW + m];
                a[mf][3] = Ksw[(kw0 + tg + 4) * LDW + m + 8];
            }
#pragma unroll
            for (int nf = 0; nf < 4; ++nf) {
                int n = wn0 + nf * 8 + g;
                bb[nf][0] = Vsw[(kw0 + tg) * LDW + n];
                bb[nf][1] = Vsw[(kw0 + tg + 4) * LDW + n];
            }
#pragma unroll
            for (int mf = 0; mf < 4; ++mf)
#pragma unroll
                for (int nf = 0; nf < 4; ++nf) mma16(acc1[mf][nf], a[mf], bb[nf]);
        }

        // ---- exp + row-sum partials + pack P into Psw ----
#pragma unroll
        for (int mf = 0; mf < 4; ++mf) {
            int r = wm0 + mf * 16 + g;
#pragma unroll
            for (int nf = 0; nf < 4; ++nf) {
                int jw = wn0 / 2 + nf * 4 + tg;
                float4 s = acc1[mf][nf];
                float px = __expf(s.x * scale);
                float py = __expf(s.y * scale);
                float pz = __expf(s.z * scale);
                float pw = __expf(s.w * scale);
                lsum[mf][0] += px + py;
                lsum[mf][1] += pz + pw;
                Psw[jw * LDW + r]     = packbf(px, py);
                Psw[jw * LDW + r + 8] = packbf(pz, pw);
            }
        }
        __syncthreads();

        // ---- mma2: acc2[i][c] += P[i][j] Q[c][j], 8 k16-steps over j ----
#pragma unroll
        for (int ks = 0; ks < 8; ++ks) {
            const int kw0 = ks * 8;
            unsigned a[4][4], bb[4][2];
#pragma unroll
            for (int mf = 0; mf < 4; ++mf) {
                int m = wm0 + mf * 16 + g;
                a[mf][0] = Psw[(kw0 + tg) * LDW + m];
                a[mf][1] = Psw[(kw0 + tg) * LDW + m + 8];
                a[mf][2] = Psw[(kw0 + tg + 4) * LDW + m];
                a[mf][3] = Psw[(kw0 + tg + 4) * LDW + m + 8];
            }
#pragma unroll
            for (int nf = 0; nf < 4; ++nf) {
                int n = wn0 + nf * 8 + g;
                bb[nf][0] = Qsw[n * LDQW + kw0 + tg];
                bb[nf][1] = Qsw[n * LDQW + kw0 + tg + 4];
            }
#pragma unroll
            for (int mf = 0; mf < 4; ++mf)
#pragma unroll
                for (int nf = 0; nf < 4; ++nf) mma16(acc2[mf][nf], a[mf], bb[nf]);
        }
        __syncthreads();
    }

    // ---- Row-sum reduction: tg-quad shuffle, then across 4 n-warps ----
#pragma unroll
    for (int mf = 0; mf < 4; ++mf)
#pragma unroll
        for (int hh = 0; hh < 2; ++hh) {
            float v = lsum[mf][hh];
            v += __shfl_xor_sync(0xffffffff, v, 1);
            v += __shfl_xor_sync(0xffffffff, v, 2);
            lsum[mf][hh] = v;
        }
    if (tg == 0) {
#pragma unroll
        for (int mf = 0; mf < 4; ++mf) {
            int r = wm0 + mf * 16 + g;
            red[wn * 128 + r]     = lsum[mf][0];
            red[wn * 128 + r + 8] = lsum[mf][1];
        }
    }
    __syncthreads();

    // ---- Normalize and write out[b][h*DH + c][i] ----
#pragma unroll
    for (int mf = 0; mf < 4; ++mf) {
        int r = wm0 + mf * 16 + g;
        float inv0 = 1.f / (red[r] + red[128 + r] + red[256 + r] + red[384 + r]);
        float inv1 = 1.f / (red[r + 8] + red[128 + r + 8] + red[256 + r + 8] + red[384 + r + 8]);
        int i0 = m0 + r;
#pragma unroll
        for (int nf = 0; nf < 4; ++nf) {
            int c = wn0 + nf * 8 + 2 * tg;
            float4 v = acc2[mf][nf];
            float* o0 = out + ((size_t)b * COUT + h * DH + c) * P_;
            float* o1 = out + ((size_t)b * COUT + h * DH + c + 1) * P_;
            o0[i0]     = v.x * inv0;
            o1[i0]     = v.y * inv0;
            o0[i0 + 8] = v.z * inv1;
            o1[i0 + 8] = v.w * inv1;
        }
    }
}

// ---------------------------------------------------------------------------
extern "C" void kernel_launch(void* const* d_in, const int* in_sizes, int n_in,
                              void* d_out, int out_size) {
    const float* x  = (const float*)d_in[0];
    const float* Wq = (const float*)d_in[1];
    const float* gq = (const float*)d_in[2];
    const float* bq = (const float*)d_in[3];
    const float* Wk = (const float*)d_in[4];
    const float* gk = (const float*)d_in[5];
    const float* bk = (const float*)d_in[6];
    const float* Wv = (const float*)d_in[7];
    const float* gv = (const float*)d_in[8];
    const float* bv = (const float*)d_in[9];
    float* out = (float*)d_out;

    static int smem_set = 0;
    if (!smem_set) {
        cudaFuncSetAttribute(attn_fused, cudaFuncAttributeMaxDynamicSharedMemorySize,
                             ASMEM_WORDS * 4);
        smem_set = 1;
    }

    proj_gemm<<<dim3(P_ / BN, COUT / BM, 3 * B_), 256>>>(x, Wq, Wk, Wv);
    bn_stats<<<3 * COUT, 256>>>(gq, bq, gk, bk, gv, bv);
    attn_fused<<<dim3(P_ / 128, B_ * H_), 256, ASMEM_WORDS * 4>>>(out);
}